// round 17
// baseline (speedup 1.0000x reference)
#include <cuda_runtime.h>
#include <cuda_fp16.h>
#include <cstdint>
#include <cstddef>

// ---------------------------------------------------------------------------
// LSTM_87351044866551  (Round 17 = R16 + ONE change: lstm v8, 1024 threads)
//   P: transpose Wi -> g_wh fp16 [N=512][K=2048]                 (unchanged)
//   G: xg = x16 @ W16, HMMA fp16, CTA 128x256, K-chunk 128       (R16 exact)
//   L: LSTM v8: 1024 thr, (col,batch)=(tid>>1,tid&1); lane pairs share a
//      column so u-loads broadcast-dedupe; 8 warps/SMSP for latency hiding.
//      Uh rows 0..103 in SMEM (stride 108), rows 104..127 in 12 u64 regs.
// ---------------------------------------------------------------------------

#define M_DIM 32768
#define N_DIM 512
#define K_DIM 2048

__device__ float g_xg[(size_t)M_DIM * N_DIM];            // 64 MB scratch
__device__ __align__(256) __half g_wh[(size_t)N_DIM * K_DIM];

// ===========================================================================
// helpers (base ISA only — tcgen05 not assemblable on this harness)
// ===========================================================================
__device__ __forceinline__ uint32_t smem_u32(const void* p) {
    uint32_t a;
    asm("{ .reg .u64 t; cvta.to.shared.u64 t, %1; cvt.u32.u64 %0, t; }"
        : "=r"(a) : "l"(p));
    return a;
}
__device__ __forceinline__ void ldsm_x4(uint32_t& r0, uint32_t& r1,
                                        uint32_t& r2, uint32_t& r3,
                                        uint32_t addr) {
    asm volatile("ldmatrix.sync.aligned.m8n8.x4.shared.b16 {%0,%1,%2,%3},[%4];"
                 : "=r"(r0), "=r"(r1), "=r"(r2), "=r"(r3) : "r"(addr));
}
__device__ __forceinline__ void mma_f16(float* d, const uint32_t* a,
                                        uint32_t b0, uint32_t b1) {
    asm volatile(
        "mma.sync.aligned.m16n8k16.row.col.f32.f16.f16.f32 "
        "{%0,%1,%2,%3},{%4,%5,%6,%7},{%8,%9},{%0,%1,%2,%3};"
        : "+f"(d[0]), "+f"(d[1]), "+f"(d[2]), "+f"(d[3])
        : "r"(a[0]), "r"(a[1]), "r"(a[2]), "r"(a[3]), "r"(b0), "r"(b1));
}
#define CPASYNC16(dst, src) \
    asm volatile("cp.async.cg.shared.global [%0],[%1],16;" :: "r"(dst), "l"(src))
#define CPCOMMIT() asm volatile("cp.async.commit_group;" ::: "memory")
#define CPWAIT0()  asm volatile("cp.async.wait_group 0;" ::: "memory")

// packed dual-fp32 FMA: d = a*b + d (lanewise) — FFMA2
__device__ __forceinline__ void ffma2(unsigned long long& d,
                                      unsigned long long a,
                                      unsigned long long b) {
    asm("fma.rn.f32x2 %0, %1, %2, %0;" : "+l"(d) : "l"(a), "l"(b));
}
__device__ __forceinline__ float f2_sum(unsigned long long d) {
    float lo, hi;
    asm("mov.b64 {%0,%1}, %2;" : "=f"(lo), "=f"(hi) : "l"(d));
    return lo + hi;
}

// ===========================================================================
// Kernel P: Wh[n][k] = fp16(Wi[k][n])
// ===========================================================================
__global__ __launch_bounds__(1024) void prep_w(const float* __restrict__ Wi) {
    __shared__ float t[32][33];
    const int k = blockIdx.x * 32 + threadIdx.y;
    const int n = blockIdx.y * 32 + threadIdx.x;
    t[threadIdx.y][threadIdx.x] = Wi[(size_t)k * N_DIM + n];
    __syncthreads();
    const int n2 = blockIdx.y * 32 + threadIdx.y;
    const int k2 = blockIdx.x * 32 + threadIdx.x;
    g_wh[(size_t)n2 * K_DIM + k2] = __float2half_rn(t[threadIdx.x][threadIdx.y]);
}

// ===========================================================================
// Kernel G: HMMA fp16 GEMM (exact R16 version): CTA 128x256, 512 thr,
// warp 32x64, K-chunk 128, 2-stage, A staged in 4 quarters.
// ===========================================================================
#define SROWB 272
#define B_OFF 34816
#define STAGE_BYTES 104448
#define GEMM_SMEM (2 * STAGE_BYTES)   // 208896
#define NCHUNK 16                     // K / 128

__global__ __launch_bounds__(512, 1) void gemm_hmma(const float* __restrict__ x) {
    extern __shared__ __half smb[];
    const uint32_t sbase = smem_u32(smb);
    const int tid  = threadIdx.x;
    const int lane = tid & 31;
    const int w    = tid >> 5;
    const int wm   = w & 3;
    const int wn   = w >> 2;
    const int m0   = blockIdx.y * 128;
    const int n0   = blockIdx.x * 256;

    float acc[2][8][4];
#pragma unroll
    for (int a = 0; a < 2; a++)
#pragma unroll
        for (int b = 0; b < 8; b++)
#pragma unroll
            for (int c = 0; c < 4; c++) acc[a][b][c] = 0.f;

    const float* xA = x + (size_t)m0 * K_DIM;
    const __half* bW = g_wh + (size_t)n0 * K_DIM;

    float4 av[2];

#define LDG_AQ(kt, q)                                                          \
    do {                                                                       \
        _Pragma("unroll")                                                      \
        for (int i = 0; i < 2; i++) {                                          \
            const int idx = tid + i * 512 + (q) * 1024;                        \
            const int r = idx >> 5, f4 = idx & 31;                             \
            av[i] = *(const float4*)(xA + (size_t)r * K_DIM + (kt) * 128 + f4 * 4); \
        }                                                                      \
    } while (0)

#define STS_AQ(s, q)                                                           \
    do {                                                                       \
        _Pragma("unroll")                                                      \
        for (int i = 0; i < 2; i++) {                                          \
            const int idx = tid + i * 512 + (q) * 1024;                        \
            const int r = idx >> 5, f4 = idx & 31;                             \
            const float4 v = av[i];                                            \
            __half2 p01, p23;                                                  \
            p01.x = __float2half_rn(v.x); p01.y = __float2half_rn(v.y);        \
            p23.x = __float2half_rn(v.z); p23.y = __float2half_rn(v.w);        \
            uint2 hp;                                                          \
            hp.x = *(uint32_t*)&p01; hp.y = *(uint32_t*)&p23;                  \
            *(uint2*)((char*)smb + (s) * STAGE_BYTES + r * SROWB + f4 * 8) = hp; \
        }                                                                      \
    } while (0)

#define CPA_B(kt, s)                                                           \
    do {                                                                       \
        _Pragma("unroll")                                                      \
        for (int i = 0; i < 8; i++) {                                          \
            const int idx = tid + i * 512;                                     \
            const int n = idx >> 4, ku = idx & 15;                             \
            const size_t gsrc = (size_t)n * K_DIM + (kt) * 128 + ku * 8;       \
            const uint32_t d =                                                 \
                sbase + (s) * STAGE_BYTES + B_OFF + n * SROWB + ku * 16;       \
            CPASYNC16(d, bW + gsrc);                                           \
        }                                                                      \
    } while (0)

    CPA_B(0, 0);
    CPCOMMIT();
#pragma unroll
    for (int q = 0; q < 4; q++) {
        LDG_AQ(0, q);
        STS_AQ(0, q);
    }
    CPWAIT0();
    __syncthreads();

    const int a_row = (lane & 7) + ((lane >> 3) & 1) * 8;
    const int a_kb  = ((lane >> 4) & 1) * 16;
    const int b_row = (lane & 7) + ((lane >> 4) & 1) * 8;
    const int b_kb  = ((lane >> 3) & 1) * 16;

    for (int kt = 0; kt < NCHUNK; kt++) {
        const int s = kt & 1;
        const bool more = (kt + 1 < NCHUNK);
        if (more) {
            CPA_B(kt + 1, s ^ 1);
            CPCOMMIT();
            LDG_AQ(kt + 1, 0);
        }

        const uint32_t stg = sbase + s * STAGE_BYTES;
#pragma unroll
        for (int kk = 0; kk < 8; kk++) {
            uint32_t ah[2][4];
#pragma unroll
            for (int mi = 0; mi < 2; mi++) {
                const uint32_t aaddr =
                    stg + (wm * 32 + mi * 16 + a_row) * SROWB + kk * 32 + a_kb;
                ldsm_x4(ah[mi][0], ah[mi][1], ah[mi][2], ah[mi][3], aaddr);
            }
#pragma unroll
            for (int np = 0; np < 4; np++) {
                const uint32_t baddr = stg + B_OFF +
                    (wn * 64 + np * 16 + b_row) * SROWB + kk * 32 + b_kb;
                uint32_t b0, b1, b2, b3;
                ldsm_x4(b0, b1, b2, b3, baddr);
#pragma unroll
                for (int mi = 0; mi < 2; mi++) {
                    mma_f16(acc[mi][np * 2],     ah[mi], b0, b1);
                    mma_f16(acc[mi][np * 2 + 1], ah[mi], b2, b3);
                }
            }
            if (more && (kk & 1) && kk < 7) {
                const int q = kk >> 1;
                STS_AQ(s ^ 1, q);
                LDG_AQ(kt + 1, q + 1);
            }
        }
        if (more) {
            STS_AQ(s ^ 1, 3);
            CPWAIT0();
        }
        __syncthreads();
    }
#undef LDG_AQ
#undef STS_AQ
#undef CPA_B

#pragma unroll
    for (int mi = 0; mi < 2; mi++)
#pragma unroll
        for (int ni = 0; ni < 8; ni++) {
            const int row = m0 + wm * 32 + mi * 16 + (lane >> 2);
            const int col = n0 + wn * 64 + ni * 8 + (lane & 3) * 2;
            float* p = g_xg + (size_t)row * N_DIM + col;
            float2 v0, v1;
            v0.x = acc[mi][ni][0]; v0.y = acc[mi][ni][1];
            v1.x = acc[mi][ni][2]; v1.y = acc[mi][ni][3];
            *(float2*)p = v0;
            *(float2*)(p + 8 * N_DIM) = v1;
        }
}

// ===========================================================================
// Kernel L: LSTM v8 — 1024 threads, col = tid>>1, batch = tid&1.
//   Lane pairs share a column: u LDS broadcast-dedupes (per-SM LDS traffic
//   unchanged vs v7) while warps/SMSP double 4->8 for latency hiding.
//   Us[512][108]: Uh rows 0..103; rows 104..127 in 12 packed u64 regs.
// ===========================================================================
__device__ __forceinline__ float fsig(float x) { return 1.f / (1.f + __expf(-x)); }
__device__ __forceinline__ float ftanh(float x) { return 1.f - 2.f / (__expf(2.f * x) + 1.f); }

#define USTRIDE 108
#define US_FLOATS (512 * USTRIDE)
#define SM2_FLOATS (US_FLOATS + 256 + 1024)   // Us + hs[2][128] + zs[2][512]

__global__ __launch_bounds__(1024, 1) void lstm_rec(const float* __restrict__ Uh,
                                                    const float* __restrict__ bias,
                                                    const float* __restrict__ Wout,
                                                    const float* __restrict__ bout,
                                                    float* __restrict__ out) {
    extern __shared__ float smf[];
    float* Us = smf;                 // [512][108], Uh rows 0..103 per column
    float* hs = smf + US_FLOATS;     // [2][128]
    float* zs = hs + 256;            // [2][512]

    const int tid   = threadIdx.x;
    const int col   = tid >> 1;      // 0..511 (gate column)
    const int batch = tid & 1;       // 0/1 within this CTA's pair
    const int b0    = blockIdx.x * 2;

    // cooperative Us load: threads 0..511 fill column tid rows 0..103
    if (tid < 512) {
        for (int k = 0; k < 104; k++) Us[tid * USTRIDE + k] = Uh[k * 512 + tid];
    }
    // Uh rows 104..127 packed as 12 f32x2 regs (both pair threads identical)
    unsigned long long wpk[12];
#pragma unroll
    for (int r = 0; r < 12; r++) {
        const float e = Uh[(104 + 2 * r) * 512 + col];
        const float o = Uh[(104 + 2 * r + 1) * 512 + col];
        asm("mov.b64 %0,{%1,%2};" : "=l"(wpk[r]) : "f"(e), "f"(o));
    }
    const float bg   = bias[col];
    const int  gate  = col >> 7;

    if (tid < 256) hs[tid] = 0.f;
    float c = 0.f;                   // carried by threads tid < 256 in combine
    __syncthreads();

    const float* xp = g_xg + ((size_t)(b0 + batch) * 128) * 512 + col;
    float xv = xp[0];

    const ulonglong2* uv2 = (const ulonglong2*)(Us + col * USTRIDE);
    const ulonglong2* hv2 = (const ulonglong2*)(hs + batch * 128);

    for (int t = 0; t < 128; t++) {
        unsigned long long za = 0ull, zb = 0ull;   // two dep chains
        // SMEM part: rows 0..103 (26 x 16B of u and h)
#pragma unroll
        for (int q = 0; q < 26; q++) {
            const ulonglong2 u = uv2[q];
            const ulonglong2 h = hv2[q];
            ffma2(za, u.x, h.x);
            ffma2(zb, u.y, h.y);
        }
        // register part: rows 104..127 (6 x 16B of h, 12 packed weight pairs)
#pragma unroll
        for (int q = 0; q < 6; q++) {
            const ulonglong2 h = hv2[26 + q];
            ffma2(za, wpk[2 * q], h.x);
            ffma2(zb, wpk[2 * q + 1], h.y);
        }
        float z = xv + bg + f2_sum(za) + f2_sum(zb);
        if (t + 1 < 128) xv = xp[(t + 1) * 512];

        float a;
        if (gate == 2) a = ftanh(z);
        else           a = fsig(z);
        zs[batch * 512 + col] = a;
        __syncthreads();

        if (tid < 256) {
            const int bl = tid >> 7;
            const int jj = tid & 127;
            const float* zrow = zs + bl * 512;
            const float ig = zrow[jj];
            const float fg = zrow[128 + jj];
            const float gg = zrow[256 + jj];
            const float og = zrow[384 + jj];
            c = fg * c + ig * gg;
            hs[bl * 128 + jj] = og * ftanh(c);
        }
        __syncthreads();
    }

    // output head
    if (tid < 256) {
        const int bl = tid >> 7;
        const int jj = tid & 127;
        const float h = hs[bl * 128 + jj];
        float p0 = h * Wout[jj * 2 + 0];
        float p1 = h * Wout[jj * 2 + 1];
#pragma unroll
        for (int off = 16; off > 0; off >>= 1) {
            p0 += __shfl_down_sync(0xffffffffu, p0, off);
            p1 += __shfl_down_sync(0xffffffffu, p1, off);
        }
        if ((tid & 31) == 0) {
            const int w = tid >> 5;
            zs[w * 2 + 0] = p0;
            zs[w * 2 + 1] = p1;
        }
    }
    __syncthreads();
    if (tid < 2) {
        float s0 = bout[0], s1 = bout[1];
#pragma unroll
        for (int w = 0; w < 4; w++) {
            s0 += zs[(tid * 4 + w) * 2 + 0];
            s1 += zs[(tid * 4 + w) * 2 + 1];
        }
        out[(b0 + tid) * 2 + 0] = s0;
        out[(b0 + tid) * 2 + 1] = s1;
    }
}

// ===========================================================================
extern "C" void kernel_launch(void* const* d_in, const int* in_sizes, int n_in,
                              void* d_out, int out_size) {
    const float* x    = (const float*)d_in[0];
    const float* Wi   = (const float*)d_in[1];
    const float* Uh   = (const float*)d_in[2];
    const float* b    = (const float*)d_in[3];
    const float* Wout = (const float*)d_in[4];
    const float* bout = (const float*)d_in[5];
    float* out = (float*)d_out;

    dim3 gp(K_DIM / 32, N_DIM / 32);
    prep_w<<<gp, dim3(32, 32)>>>(Wi);

    cudaFuncSetAttribute(gemm_hmma, cudaFuncAttributeMaxDynamicSharedMemorySize,
                         GEMM_SMEM);
    dim3 gg(N_DIM / 256, M_DIM / 128);          // (2, 256) = 512 CTAs
    gemm_hmma<<<gg, 512, GEMM_SMEM>>>(x);

    const size_t smem2 = SM2_FLOATS * sizeof(float);  // 226,304 B
    cudaFuncSetAttribute(lstm_rec, cudaFuncAttributeMaxDynamicSharedMemorySize,
                         (int)smem2);
    lstm_rec<<<128, 1024, smem2>>>(Uh, b, Wout, bout, out);
}